// round 1
// baseline (speedup 1.0000x reference)
#include <cuda_runtime.h>
#include <cstdint>

// Problem constants (fixed-shape problem)
#define QD 50      // qubits
#define SD 64      // heads
#define SP 32      // s-pairs (SD/2), packed 2 heads per f32x2
#define EPSF 1e-12f

// -------- scratch (no allocation allowed; __device__ globals) --------
__device__ __align__(16) float g_headsPacked[QD * SP * 4]; // [q][s_pair]{h0e,h0o,h1e,h1o}
__device__ __align__(16) float g_w[SD];                    // hr_s * rho_s
__device__ float g_partials[4096];                         // per-CTA partial sums

typedef unsigned long long ull;

// -------- f32x2 packed math (sm_100+ PTX; FFMA2 in SASS) --------
__device__ __forceinline__ ull fma2(ull a, ull b, ull c) {
    ull d;
    asm("fma.rn.f32x2 %0, %1, %2, %3;" : "=l"(d) : "l"(a), "l"(b), "l"(c));
    return d;
}
__device__ __forceinline__ ull mul2(ull a, ull b) {
    ull d;
    asm("mul.rn.f32x2 %0, %1, %2;" : "=l"(d) : "l"(a), "l"(b));
    return d;
}
__device__ __forceinline__ ull bcast2(float x) {
    ull d;
    asm("mov.b64 %0, {%1, %1};" : "=l"(d) : "f"(x));
    return d;
}
__device__ __forceinline__ float2 unpack2(ull v) {
    float2 r;
    asm("mov.b64 {%0, %1}, %2;" : "=f"(r.x), "=f"(r.y) : "l"(v));
    return r;
}

__device__ __forceinline__ float softplus20(float x) {
    float z = 20.0f * x;
    // stable: for large z, log1p(exp(z)) ~ z (diff < 2e-9 rel at z>20)
    return (z > 20.0f) ? z : log1pf(expf(z));
}

// =====================================================================
// Kernel 1: preprocess heads + head ratios (tiny; 1 CTA)
//   heads: softplus(20x), L1-normalize over p.
//   Reference divides by max(sum,EPS); we factor the clamp as a per-(s,q)
//   scale sigma = min(1, sum/EPS) and fold rho_s = prod_q sigma into the
//   head-ratio weight, so the mainloop can use the exact-sum-1 identity
//   dot = b2 + h0*(b0-b2) + h1*(b1-b2).
// =====================================================================
__global__ void prep_kernel(const float* __restrict__ hp,
                            const float* __restrict__ hrp) {
    __shared__ float s_sigma[SD * QD];
    __shared__ float s_sp[SD];
    __shared__ float s_tot;
    int tid = threadIdx.x;

    for (int idx = tid; idx < SD * QD; idx += blockDim.x) {
        int s = idx / QD, q = idx - s * QD;
        const float* h = hp + (size_t)(s * QD + q) * 3;
        float h0 = softplus20(h[0]);
        float h1 = softplus20(h[1]);
        float h2 = softplus20(h[2]);
        float sum3 = h0 + h1 + h2;
        float sigma, g0, g1;
        if (sum3 > 0.0f) {
            sigma = fminf(1.0f, sum3 * 1e12f);
            g0 = h0 / sum3;
            g1 = h1 / sum3;
        } else {
            sigma = 0.0f; g0 = 0.0f; g1 = 0.0f;  // head contributes 0 (matches ref: dot=0)
        }
        s_sigma[idx] = sigma;
        int base = (q * SP + (s >> 1)) * 4;
        int o = s & 1;
        g_headsPacked[base + o]     = g0;
        g_headsPacked[base + 2 + o] = g1;
    }
    if (tid < SD) s_sp[tid] = softplus20(hrp[tid]);
    __syncthreads();
    if (tid == 0) {
        float t = 0.0f;
        for (int s = 0; s < SD; s++) t += s_sp[s];
        s_tot = t;
    }
    __syncthreads();
    if (tid < SD) {
        float w = s_sp[tid] / fmaxf(s_tot, EPSF);
        w = (w + 0.001f / (float)SD) / 1.001f;
        float rho = 1.0f;
        for (int q = 0; q < QD; q++) rho *= s_sigma[tid * QD + q];
        g_w[tid] = w * rho;
    }
}

// =====================================================================
// Kernel 2: main — one n per thread, 64 heads packed as 32 f32x2 lanes.
// Inner step: 1 LDS.128 + 3 FFMA2-class ops. FMA-pipe bound by design.
// =====================================================================
__global__ void __launch_bounds__(128)
main_kernel(const float* __restrict__ bp, const float* __restrict__ coeff, int N) {
    __shared__ ulonglong2 sH[QD * SP];   // 25.6 KB
    __shared__ ull sW[SP];
    __shared__ float s_warp[4];
    int tid = threadIdx.x;

    // stage packed heads into smem (broadcast-read later)
    {
        const float4* gH = (const float4*)g_headsPacked;
        float4* sH4 = (float4*)sH;
        for (int i = tid; i < QD * SP; i += 128) sH4[i] = gH[i];
        if (tid < SP) sW[tid] = ((const ull*)g_w)[tid];  // {w_even, w_odd}
    }
    __syncthreads();

    int n = blockIdx.x * 128 + tid;
    float contrib = 0.0f;
    if (n < N) {
        const float* row = bp + (size_t)n * (QD * 3);
        ull prod[SP];
        #pragma unroll
        for (int i = 0; i < SP; i++) prod[i] = 0x3f8000003f800000ull; // {1.f,1.f}

        for (int q = 0; q < QD; q++) {
            float b0 = row[3 * q + 0];
            float b1 = row[3 * q + 1];
            float b2 = row[3 * q + 2];
            ull d0p = bcast2(b0 - b2);
            ull d1p = bcast2(b1 - b2);
            ull b2p = bcast2(b2);
            const ulonglong2* hq = sH + q * SP;
            #pragma unroll
            for (int i = 0; i < SP; i++) {
                ulonglong2 h = hq[i];                 // LDS.128: {h0pair, h1pair}
                ull m = fma2(h.x, d0p, b2p);          // b2 + h0*(b0-b2)
                m = fma2(h.y, d1p, m);                //    + h1*(b1-b2)
                prod[i] = mul2(prod[i], m);           // running product over q
            }
        }

        ull acc = 0ull;                               // {0.f, 0.f}
        #pragma unroll
        for (int i = 0; i < SP; i++) acc = fma2(prod[i], sW[i], acc);
        float2 a = unpack2(acc);
        float cov = a.x + a.y;
        float c = coeff[n];
        contrib = c * c / cov;
    }

    // block reduction (deterministic order)
    #pragma unroll
    for (int o = 16; o > 0; o >>= 1)
        contrib += __shfl_down_sync(0xffffffffu, contrib, o);
    if ((tid & 31) == 0) s_warp[tid >> 5] = contrib;
    __syncthreads();
    if (tid == 0)
        g_partials[blockIdx.x] = (s_warp[0] + s_warp[1]) + (s_warp[2] + s_warp[3]);
}

// =====================================================================
// Kernel 3: deterministic final reduction over CTA partials
// =====================================================================
__global__ void reduce_kernel(float* __restrict__ out, int nb) {
    __shared__ float sh[256];
    int tid = threadIdx.x;
    float v = 0.0f;
    for (int i = tid; i < nb; i += 256) v += g_partials[i];
    sh[tid] = v;
    __syncthreads();
    for (int s = 128; s > 0; s >>= 1) {
        if (tid < s) sh[tid] += sh[tid + s];
        __syncthreads();
    }
    if (tid == 0) out[0] = sh[0];
}

extern "C" void kernel_launch(void* const* d_in, const int* in_sizes, int n_in,
                              void* d_out, int out_size) {
    const float* bp    = (const float*)d_in[0];  // batch_pauli_tensor [N,Q,3]
    const float* coeff = (const float*)d_in[1];  // batch_coeff [N]
    const float* hp    = (const float*)d_in[2];  // heads_param [S,Q,3]
    const float* hrp   = (const float*)d_in[3];  // head_ratios_param [S]
    int N = in_sizes[1];

    prep_kernel<<<1, 128>>>(hp, hrp);
    int nb = (N + 127) / 128;
    if (nb > 4096) nb = 4096;  // g_partials bound (N=100000 -> 782)
    main_kernel<<<nb, 128>>>(bp, coeff, N);
    reduce_kernel<<<1, 256>>>((float*)d_out, nb);
}